// round 16
// baseline (speedup 1.0000x reference)
#include <cuda_runtime.h>
#include <cuda_bf16.h>
#include <cstdint>

#define BSZ 8192
#define DD  512
#define CC  512
#define MT  64                  // rows per CTA
#define NTC 256                 // classes per CTA (N half)
#define NBLK 256                // 256 CTAs -> 2 per SM, independent barrier domains
#define NPAIR 128
#define NSTG 8                  // K chunks of 64
#define TH  3.0f
#define SLOTS 16                // local slots; merged list capacity 32
#define NTH 512

// ---- device scratch ----
__device__ __nv_bfloat16 g_ch[CC * DD];
__device__ float g_cnorm[CC];
__device__ int   g_present[CC];          // zero-init; only 1s written (idempotent)
__device__ int   g_gcnt[NBLK * MT];      // per-CTA per-row candidate counts
__device__ unsigned short g_gcand[NBLK * MT * SLOTS];
__device__ int   g_pairc[NPAIR];         // zero-init; reset by merger each call
__device__ float g_rpart[2 * NPAIR];
__device__ int   g_rcount;               // reset by last merger each call

// ---- main smem layout (bytes) ----
#define SM_CN    0                   // 512 f (full, for refine)
#define SM_TG    2048                // 64 i
#define SM_XN    2304                // 64 f
#define SM_RM    2560                // 64 f
#define SM_SCNT  2816                // 64 i
#define SM_CAND  3072                // 64*32 u16 = 4096 (merged capacity)
#define SM_RED   7168                // 64*4 f = 1024
#define SM_LP    8192                // 64*2 f = 512
#define SM_FIN   8704                // 16 f
#define SM_TILE  9216                // 1024-aligned
#define OFF_A    0                   // 64 rows x 128B = 8192
#define OFF_B    8192                // 256 rows x 128B = 32768
#define STG_S    40960               // one stage (A+B)
#define SMEM_BYTES (SM_TILE + 2 * STG_S)   // 91136 -> 2 CTAs/SM

static __device__ __forceinline__ uint32_t s2u(const void* p) {
    uint32_t a;
    asm("{ .reg .u64 t; cvta.to.shared.u64 t, %1; cvt.u32.u64 %0, t; }" : "=r"(a) : "l"(p));
    return a;
}
static __device__ __forceinline__ void cp16(uint32_t dst, const void* src) {
    asm volatile("cp.async.cg.shared.global [%0], [%1], 16;" :: "r"(dst), "l"(src));
}
#define LDSM4(r0, r1, r2, r3, addr)                                             \
    asm volatile("ldmatrix.sync.aligned.m8n8.x4.shared.b16 {%0,%1,%2,%3}, [%4];" \
                 : "=r"(r0), "=r"(r1), "=r"(r2), "=r"(r3) : "r"(addr))
#define MMA(d, a, b0, b1)                                                        \
    asm volatile("mma.sync.aligned.m16n8k16.row.col.f32.bf16.bf16.f32 "          \
                 "{%0,%1,%2,%3},{%4,%5,%6,%7},{%8,%9},{%0,%1,%2,%3};"            \
                 : "+f"((d)[0]), "+f"((d)[1]), "+f"((d)[2]), "+f"((d)[3])        \
                 : "r"((a)[0]), "r"((a)[1]), "r"((a)[2]), "r"((a)[3]),           \
                   "r"(b0), "r"(b1))

static __device__ __forceinline__ uint32_t packbf(float x, float y) {
    return ((uint32_t)__bfloat16_as_ushort(__float2bfloat16(y)) << 16)
         | __bfloat16_as_ushort(__float2bfloat16(x));
}
static __device__ __forceinline__ uint4 cvt8(float4 a, float4 b) {
    uint4 r;
    r.x = packbf(a.x, a.y); r.y = packbf(a.z, a.w);
    r.z = packbf(b.x, b.y); r.w = packbf(b.z, b.w);
    return r;
}
static __device__ __forceinline__ float sq4(float4 v, float s) {
    s = fmaf(v.x, v.x, s); s = fmaf(v.y, v.y, s);
    s = fmaf(v.z, v.z, s); s = fmaf(v.w, v.w, s);
    return s;
}
static __device__ __forceinline__ float dot512(const float4* xv, const float* crow, int lane) {
    const float4* c4 = (const float4*)crow;
    float s = 0.f;
#pragma unroll
    for (int i = 0; i < 4; i++) {
        float4 c = c4[lane + 32 * i];
        s = fmaf(xv[i].x, c.x, s); s = fmaf(xv[i].y, c.y, s);
        s = fmaf(xv[i].z, c.z, s); s = fmaf(xv[i].w, c.w, s);
    }
#pragma unroll
    for (int o = 16; o > 0; o >>= 1) s += __shfl_xor_sync(0xffffffffu, s, o);
    return s;
}

// ---------------------------------------------------------------------------
// prep (small): centers f32->bf16 + cnorm (blocks 0..63); presence marks (64..67)
// ---------------------------------------------------------------------------
__global__ void prep_kernel(const float* __restrict__ CT, const int* __restrict__ T) {
    if (blockIdx.x >= 64) {
        int base = (blockIdx.x - 64) * 2048 + threadIdx.x;
#pragma unroll
        for (int k = 0; k < 8; k++) g_present[T[base + 256 * k]] = 1;
        return;
    }
    int row  = blockIdx.x * 8 + (threadIdx.x >> 5);
    int lane = threadIdx.x & 31;
    const float* src = CT + (size_t)row * DD;
    float s = 0.f;
    const float4* p4 = (const float4*)src;
#pragma unroll
    for (int i = 0; i < 4; i++) {
        float4 v = p4[lane + 32 * i];
        s = sq4(v, s);
        uint2 hv;
        hv.x = packbf(v.x, v.y);
        hv.y = packbf(v.z, v.w);
        *(uint2*)(g_ch + (size_t)row * DD + (size_t)(lane + 32 * i) * 4) = hv;
    }
#pragma unroll
    for (int o = 16; o > 0; o >>= 1) s += __shfl_xor_sync(0xffffffffu, s, o);
    if (lane == 0) g_cnorm[row] = s;
}

// ---------------------------------------------------------------------------
// main: pair-split GEMM. CTA (mt,nh) computes M64 x N256 (its N half),
// 16 warps in 4x4 grid, warp tile m16 x n64, double-buffered, 64 regs ->
// 2 independent CTAs per SM. Second-arriving CTA of each pair merges
// candidates and runs the exact fp32 refine + global reduction.
// ---------------------------------------------------------------------------
__global__ __launch_bounds__(NTH, 2) void main_kernel(
    const float* __restrict__ X, const float* __restrict__ CT,
    const int* __restrict__ T, float* out, int out_size)
{
    extern __shared__ char smem[];
    const uint32_t sb = s2u(smem);
    const int tid = threadIdx.x, lane = tid & 31, wid = tid >> 5;
    const int wr = wid >> 2, wc = wid & 3;
    const int bid = blockIdx.x, mt = bid >> 1, nh = bid & 1;
    const float INF = __int_as_float(0x7f800000);

    float* cn     = (float*)(smem + SM_CN);
    int*   tg     = (int*)(smem + SM_TG);
    float* sxn    = (float*)(smem + SM_XN);
    float* rowmin = (float*)(smem + SM_RM);
    int*   scnt   = (int*)(smem + SM_SCNT);
    unsigned short* scand = (unsigned short*)(smem + SM_CAND);   // stride 32/row
    float* red    = (float*)(smem + SM_RED);
    float* lp     = (float*)(smem + SM_LP);
    float* fin    = (float*)(smem + SM_FIN);

    // ---- prep-independent prologue (overlaps prep via PDL) ----
    if (tid < MT) { tg[tid] = T[mt * MT + tid]; scnt[tid] = 0; }

    // A producer: 64 rows x 8 threads; each converts 2 float4 -> uint4
    const int arow = tid >> 3, aq = tid & 7;
    const float4* Ag = (const float4*)(X + (size_t)(mt * MT + arow) * DD);
    const uint32_t aoff0 = (uint32_t)(arow * 128 + aq * 16);
    const uint32_t aoff_sw = aoff0 ^ ((aoff0 >> 3) & 0x70);
    float sq = 0.f;

#pragma unroll
    for (int st = 0; st < 2; st++) {
        float4 u0 = Ag[st * 16 + aq * 2], u1 = Ag[st * 16 + aq * 2 + 1];
        sq = sq4(u0, sq); sq = sq4(u1, sq);
        *(uint4*)(smem + SM_TILE + st * STG_S + OFF_A + aoff_sw) = cvt8(u0, u1);
    }
    float4 ar0 = Ag[2 * 16 + aq * 2], ar1 = Ag[2 * 16 + aq * 2 + 1];

    // ---- wait for prep outputs ----
    asm volatile("griddepcontrol.wait;" ::: "memory");

    if (tid < CC) cn[tid] = g_present[tid] ? g_cnorm[tid] : INF;

    // B producer: 256 rows x 8 chunks = 2048 cp16 / 512 threads = 4 each
#define BFILL(ST)                                                                 \
    do {                                                                          \
        const int st_ = (ST);                                                     \
        const uint32_t dstb_ = sb + SM_TILE + (uint32_t)(st_ & 1) * STG_S + OFF_B;\
        _Pragma("unroll")                                                         \
        for (int i_ = 0; i_ < 4; i_++) {                                          \
            int idx_ = tid + i_ * NTH;                                            \
            int row_ = idx_ >> 3, q_ = idx_ & 7;                                  \
            uint32_t off_ = (uint32_t)(row_ * 128 + q_ * 16);                     \
            off_ ^= ((off_ >> 3) & 0x70);                                         \
            cp16(dstb_ + off_,                                                    \
                 g_ch + (size_t)(nh * NTC + row_) * DD + st_ * 64 + q_ * 8);      \
        }                                                                         \
        asm volatile("cp.async.commit_group;");                                   \
    } while (0)

    BFILL(0);
    BFILL(1);

    float acc[8][4];
#pragma unroll
    for (int j = 0; j < 8; j++)
#pragma unroll
        for (int e = 0; e < 4; e++) acc[j][e] = 0.f;

    const int rA       = wr * 16 + (lane & 15);
    const uint32_t swz = (uint32_t)(lane & 7) << 4;
    const uint32_t kA  = (uint32_t)(lane >> 4) << 4;
    const uint32_t kB  = (uint32_t)((lane >> 3) & 1) << 4;
    const int nB       = ((lane >> 4) << 3) + (lane & 7);

    for (int kt = 0; kt < NSTG; kt++) {
        if (kt == NSTG - 1) asm volatile("cp.async.wait_group 0;");
        else                asm volatile("cp.async.wait_group 1;");
        __syncthreads();

        const uint32_t tb    = sb + SM_TILE + (uint32_t)(kt & 1) * STG_S;
        const uint32_t aA0   = tb + OFF_A + (uint32_t)rA * 128;
        const uint32_t bbase = tb + OFF_B + (uint32_t)((wc * 64 + nB) * 128);

#pragma unroll
        for (int kk = 0; kk < 4; kk++) {
            const uint32_t ka = ((uint32_t)(kk * 32) + kA) ^ swz;
            const uint32_t kb = ((uint32_t)(kk * 32) + kB) ^ swz;
            uint32_t a[4];
            LDSM4(a[0], a[1], a[2], a[3], aA0 + ka);
#pragma unroll
            for (int nb = 0; nb < 4; nb++) {
                uint32_t b[4];
                LDSM4(b[0], b[1], b[2], b[3], bbase + (uint32_t)(nb * 2048) + kb);
                MMA(acc[nb * 2 + 0], a, b[0], b[1]);
                MMA(acc[nb * 2 + 1], a, b[2], b[3]);
            }
        }
        __syncthreads();
        if (kt + 2 < NSTG) {
            sq = sq4(ar0, sq); sq = sq4(ar1, sq);
            *(uint4*)(smem + SM_TILE + (size_t)(kt & 1) * STG_S + OFF_A + aoff_sw)
                = cvt8(ar0, ar1);
            BFILL(kt + 2);
            if (kt + 3 < NSTG) {
                ar0 = Ag[(kt + 3) * 16 + aq * 2];
                ar1 = Ag[(kt + 3) * 16 + aq * 2 + 1];
            }
        }
    }
#undef BFILL

    // ---- row norms: reduce over the 8 q-threads of each row ----
    sq += __shfl_xor_sync(0xffffffffu, sq, 1);
    sq += __shfl_xor_sync(0xffffffffu, sq, 2);
    sq += __shfl_xor_sync(0xffffffffu, sq, 4);
    if (aq == 0) sxn[arow] = sq;

    // ---- pass 1: approx row-min over non-own classes (this N half) ----
    float rmin[2] = {INF, INF};
#pragma unroll
    for (int j = 0; j < 8; j++) {
        const int colb = wc * 64 + j * 8 + (lane & 3) * 2;
#pragma unroll
        for (int e = 0; e < 4; e++) {
            const int cl = nh * NTC + colb + (e & 1);
            const int lr = wr * 16 + ((e >> 1) << 3) + (lane >> 2);
            const float v = fmaf(-2.f, acc[j][e], cn[cl]);
            if (cl != tg[lr]) rmin[e >> 1] = fminf(rmin[e >> 1], v);
        }
    }
#pragma unroll
    for (int rr = 0; rr < 2; rr++) {
        float m = rmin[rr];
        m = fminf(m, __shfl_xor_sync(0xffffffffu, m, 1));
        m = fminf(m, __shfl_xor_sync(0xffffffffu, m, 2));
        if ((lane & 3) == 0)
            red[(wr * 16 + rr * 8 + (lane >> 2)) * 4 + wc] = m;
    }
    __syncthreads();
    if (tid < MT)
        rowmin[tid] = fminf(fminf(red[tid * 4 + 0], red[tid * 4 + 1]),
                            fminf(red[tid * 4 + 2], red[tid * 4 + 3]));
    __syncthreads();

    // ---- pass 2: mark candidates (local list, global class ids) ----
#pragma unroll
    for (int j = 0; j < 8; j++) {
        const int colb = wc * 64 + j * 8 + (lane & 3) * 2;
#pragma unroll
        for (int e = 0; e < 4; e++) {
            const int cl = nh * NTC + colb + (e & 1);
            const int lr = wr * 16 + ((e >> 1) << 3) + (lane >> 2);
            const float v = fmaf(-2.f, acc[j][e], cn[cl]);
            if (cl != tg[lr] && v < 1.0e30f && v <= rowmin[lr] + TH) {
                int s = atomicAdd(&scnt[lr], 1);
                if (s < SLOTS) scand[lr * 32 + s] = (unsigned short)cl;
            }
        }
    }
    __syncthreads();

    // ---- publish local candidates; second-arriving CTA of the pair merges ----
    __shared__ int smerge;
    if (tid < MT) {
        int c = scnt[tid]; if (c > SLOTS) c = SLOTS;
        scnt[tid] = c;
        g_gcnt[bid * MT + tid] = c;
        uint4* dst = (uint4*)(g_gcand + (size_t)(bid * MT + tid) * SLOTS);
        uint4* src = (uint4*)(scand + tid * 32);
        dst[0] = src[0];
        dst[1] = src[1];
    }
    __syncthreads();
    if (tid == 0) {
        __threadfence();
        smerge = (atomicAdd(&g_pairc[mt], 1) == 1);
        if (smerge) g_pairc[mt] = 0;       // reset for next graph replay
    }
    __syncthreads();
    if (!smerge) return;                    // first-arriving CTA done

    __threadfence();                        // acquire peer's published data
    const int po = bid ^ 1;
    if (tid < MT) {
        int c1 = scnt[tid];
        int c2 = g_gcnt[po * MT + tid]; if (c2 > SLOTS) c2 = SLOTS;
        const unsigned short* pc = g_gcand + (size_t)(po * MT + tid) * SLOTS;
        for (int i = 0; i < c2; i++) scand[tid * 32 + c1 + i] = pc[i];
        scnt[tid] = c1 + c2;
    }
    __syncthreads();

    // ---- refine: exact fp32 dots over merged list; warp w rows w*4..w*4+3 ----
#pragma unroll 1
    for (int rr = 0; rr < 4; rr++) {
        const int lr = wid * 4 + rr;
        const int grow = mt * MT + lr;
        const float4* xr = (const float4*)(X + (size_t)grow * DD);
        float4 xv[4];
#pragma unroll
        for (int i = 0; i < 4; i++) xv[i] = xr[lane + 32 * i];
        const int own = tg[lr];
        const float dot_own = dot512(xv, CT + (size_t)own * DD, lane);
        const int cnt = scnt[lr];
        float vmin = INF;
        for (int i = 0; i < cnt; i++) {
            int c = scand[lr * 32 + i];
            float d = dot512(xv, CT + (size_t)c * DD, lane);
            vmin = fminf(vmin, cn[c] - 2.f * d);
        }
        const float xn = sxn[lr];
        float dap = sqrtf(fmaxf(xn + cn[own] - 2.f * dot_own, 1e-12f));
        float dan = sqrtf(fmaxf(xn + vmin, 1e-12f));
        if (lane == 0) {
            lp[2 * lr]     = fmaxf(0.f, dap - dan + 1.f);
            lp[2 * lr + 1] = (dan > dap) ? 1.f : 0.f;
        }
    }
    __syncthreads();

    // ---- per-pair reduction + global last-block finish (128 mergers) ----
    __shared__ int slast;
    if (tid < MT) {
        float li = lp[2 * tid], pi = lp[2 * tid + 1];
#pragma unroll
        for (int o = 16; o > 0; o >>= 1) {
            li += __shfl_xor_sync(0xffffffffu, li, o);
            pi += __shfl_xor_sync(0xffffffffu, pi, o);
        }
        if ((tid & 31) == 0) { fin[tid >> 5] = li; fin[4 + (tid >> 5)] = pi; }
    }
    __syncthreads();
    if (tid == 0) {
        g_rpart[2 * mt]     = fin[0] + fin[1];
        g_rpart[2 * mt + 1] = fin[4] + fin[5];
        __threadfence();
        slast = (atomicAdd(&g_rcount, 1) == NPAIR - 1);
    }
    __syncthreads();
    if (slast) {
        float a = 0.f, b = 0.f;
        if (tid < NPAIR) { a = g_rpart[2 * tid]; b = g_rpart[2 * tid + 1]; }
#pragma unroll
        for (int o = 16; o > 0; o >>= 1) {
            a += __shfl_xor_sync(0xffffffffu, a, o);
            b += __shfl_xor_sync(0xffffffffu, b, o);
        }
        if (tid < NPAIR && (tid & 31) == 0) { fin[tid >> 5] = a; fin[4 + (tid >> 5)] = b; }
        __syncthreads();
        if (tid == 0) {
            float sa = fin[0] + fin[1] + fin[2] + fin[3];
            float sb = fin[4] + fin[5] + fin[6] + fin[7];
            out[0] = sa / (float)BSZ;
            if (out_size > 1) out[1] = sb / (float)BSZ;
            g_rcount = 0;            // reset for next graph replay
        }
    }
}

// ---------------------------------------------------------------------------
extern "C" void kernel_launch(void* const* d_in, const int* in_sizes, int n_in,
                              void* d_out, int out_size) {
    const float* X  = nullptr;
    const float* CT = nullptr;
    const int*   T  = nullptr;
    for (int i = 0; i < n_in; i++) {
        if (in_sizes[i] == BSZ * DD)     X  = (const float*)d_in[i];
        else if (in_sizes[i] == CC * DD) CT = (const float*)d_in[i];
        else if (in_sizes[i] == BSZ)     T  = (const int*)d_in[i];
    }
    cudaFuncSetAttribute(main_kernel,
                         cudaFuncAttributeMaxDynamicSharedMemorySize, SMEM_BYTES);

    prep_kernel<<<68, 256>>>(CT, T);

    // PDL launch: main overlaps prep with its prep-independent prologue.
    cudaLaunchConfig_t cfg = {};
    cfg.gridDim = dim3(NBLK);
    cfg.blockDim = dim3(NTH);
    cfg.dynamicSmemBytes = SMEM_BYTES;
    cfg.stream = 0;
    cudaLaunchAttribute attrs[1];
    attrs[0].id = cudaLaunchAttributeProgrammaticStreamSerialization;
    attrs[0].val.programmaticStreamSerializationAllowed = 1;
    cfg.attrs = attrs;
    cfg.numAttrs = 1;
    cudaLaunchKernelEx(&cfg, main_kernel, X, CT, T, (float*)d_out, out_size);
}